// round 2
// baseline (speedup 1.0000x reference)
#include <cuda_runtime.h>
#include <cuda_bf16.h>

// Problem constants (fixed shapes for BevPoolV2_8478265442577)
#define B_     1
#define N_CAM  6
#define D_BINS 118
#define HF     32
#define WF     88
#define C_     80
#define DZ     1
#define DY     128
#define DX     128

#define N_DEPTH (B_ * N_CAM * D_BINS * HF * WF)   // 1,993,728
#define N_FEAT  (B_ * N_CAM * HF * WF * C_)       // 1,351,680
#define N_PTS   1000000
#define N_BEV   (B_ * DZ * DY * DX)               // 16,384 (spatial stride S)
#define S_      (DZ * DY * DX)                    // 16,384

// ---------------------------------------------------------------------------
// Zero-init the output (harness poisons d_out with 0xAA; empty bins must be 0)
// ---------------------------------------------------------------------------
__global__ void zero_kernel(float4* __restrict__ out, int n4) {
    int i = blockIdx.x * blockDim.x + threadIdx.x;
    int stride = gridDim.x * blockDim.x;
    for (; i < n4; i += stride)
        out[i] = make_float4(0.f, 0.f, 0.f, 0.f);
}

// ---------------------------------------------------------------------------
// One warp per interval. Lane l accumulates channels {l, l+32, l+64}.
// Intervals are disjoint BEV bins -> plain stores, no atomics.
// ---------------------------------------------------------------------------
__global__ void bev_pool_kernel(const float* __restrict__ depth,
                                const float* __restrict__ feat,
                                const int*   __restrict__ ranks_depth,
                                const int*   __restrict__ ranks_feat,
                                const int*   __restrict__ ranks_bev,
                                const int*   __restrict__ istart,
                                const int*   __restrict__ ilen,
                                int n_intervals,
                                float* __restrict__ out) {
    int gwarp = (blockIdx.x * blockDim.x + threadIdx.x) >> 5;
    int lane  = threadIdx.x & 31;
    if (gwarp >= n_intervals) return;

    int start = istart[gwarp];
    int len   = ilen[gwarp];

    const int c0 = lane;
    const int c1 = lane + 32;
    const int c2 = lane + 64;            // valid only for lanes 0..15 (C=80)
    const bool has_c2 = (c2 < C_);

    float a0 = 0.f, a1 = 0.f, a2 = 0.f;

    int i = 0;
    // 2x unroll for memory-level parallelism
    for (; i + 2 <= len; i += 2) {
        int p0 = start + i;
        int p1 = p0 + 1;
        int rd0 = __ldg(&ranks_depth[p0]);
        int rd1 = __ldg(&ranks_depth[p1]);
        int rf0 = __ldg(&ranks_feat[p0]);
        int rf1 = __ldg(&ranks_feat[p1]);
        float d0 = __ldg(&depth[rd0]);
        float d1 = __ldg(&depth[rd1]);
        const float* fr0 = feat + (size_t)rf0 * C_;
        const float* fr1 = feat + (size_t)rf1 * C_;
        float f00 = __ldg(fr0 + c0);
        float f01 = __ldg(fr0 + c1);
        float f10 = __ldg(fr1 + c0);
        float f11 = __ldg(fr1 + c1);
        a0 = fmaf(d0, f00, a0);
        a1 = fmaf(d0, f01, a1);
        a0 = fmaf(d1, f10, a0);
        a1 = fmaf(d1, f11, a1);
        if (has_c2) {
            float f02 = __ldg(fr0 + c2);
            float f12 = __ldg(fr1 + c2);
            a2 = fmaf(d0, f02, a2);
            a2 = fmaf(d1, f12, a2);
        }
    }
    for (; i < len; i++) {
        int p = start + i;
        int rd = __ldg(&ranks_depth[p]);
        int rf = __ldg(&ranks_feat[p]);
        float d = __ldg(&depth[rd]);
        const float* fr = feat + (size_t)rf * C_;
        a0 = fmaf(d, __ldg(fr + c0), a0);
        a1 = fmaf(d, __ldg(fr + c1), a1);
        if (has_c2) a2 = fmaf(d, __ldg(fr + c2), a2);
    }

    // Output layout: (B, C, Dz, Dy, Dx). bev = b*S + s  ->  idx = b*C*S + c*S + s
    int bev = __ldg(&ranks_bev[start]);
    int b   = bev / S_;
    int s   = bev - b * S_;
    float* o = out + (size_t)b * C_ * S_ + s;
    o[(size_t)c0 * S_] = a0;
    o[(size_t)c1 * S_] = a1;
    if (has_c2) o[(size_t)c2 * S_] = a2;
}

// ---------------------------------------------------------------------------
extern "C" void kernel_launch(void* const* d_in, const int* in_sizes, int n_in,
                              void* d_out, int out_size) {
    const float* depth = nullptr;
    const float* feat  = nullptr;
    const int*   ranks[3] = {nullptr, nullptr, nullptr};
    int nrk = 0;
    const int* small_arr[2] = {nullptr, nullptr};
    int small_sz[2] = {0, 0};
    int nsmall = 0;

    for (int i = 0; i < n_in; i++) {
        int sz = in_sizes[i];
        if (sz == N_DEPTH && !depth) {
            depth = (const float*)d_in[i];
        } else if (sz == N_FEAT && !feat) {
            feat = (const float*)d_in[i];
        } else if (sz == N_PTS && nrk < 3) {
            ranks[nrk++] = (const int*)d_in[i];   // order: depths, feats, bevs
        } else if (sz == 5) {
            // bev_feat_shape metadata — shapes are compile-time constants here
        } else if (nsmall < 2) {
            small_arr[nsmall] = (const int*)d_in[i];  // order: starts, lengths
            small_sz[nsmall] = sz;
            nsmall++;
        }
    }

    const int* istart = small_arr[0];
    const int* ilen   = small_arr[1];
    int n_intervals   = small_sz[0];

    float* out = (float*)d_out;

    // 1) zero the output
    int n4 = out_size / 4;   // out_size = 1,310,720 (divisible by 4)
    zero_kernel<<<256, 256>>>((float4*)out, n4);

    // 2) pooled gather-multiply-store, one warp per interval
    const int threads = 256;                    // 8 warps per block
    int blocks = (n_intervals + 7) / 8;
    if (blocks < 1) blocks = 1;
    bev_pool_kernel<<<blocks, threads>>>(depth, feat,
                                         ranks[0], ranks[1], ranks[2],
                                         istart, ilen, n_intervals, out);
}

// round 3
// speedup vs baseline: 1.1066x; 1.1066x over previous
#include <cuda_runtime.h>
#include <cuda_bf16.h>

// Problem constants (fixed shapes for BevPoolV2_8478265442577)
#define B_     1
#define N_CAM  6
#define D_BINS 118
#define HF     32
#define WF     88
#define C_     80
#define DZ     1
#define DY     128
#define DX     128

#define N_DEPTH (B_ * N_CAM * D_BINS * HF * WF)   // 1,993,728
#define N_FEAT  (B_ * N_CAM * HF * WF * C_)       // 1,351,680
#define N_PTS   1000000
#define S_      (DZ * DY * DX)                    // 16,384

// ---------------------------------------------------------------------------
// Zero-init the output (harness poisons d_out with 0xAA; empty bins must be 0)
// ---------------------------------------------------------------------------
__global__ void zero_kernel(float4* __restrict__ out, int n4) {
    int i = blockIdx.x * blockDim.x + threadIdx.x;
    int stride = gridDim.x * blockDim.x;
    for (; i < n4; i += stride)
        out[i] = make_float4(0.f, 0.f, 0.f, 0.f);
}

// ---------------------------------------------------------------------------
// One warp per interval.
// Feat layout: lane l (0..19) owns channels [4l, 4l+4) as one float4.
// Per 16-point chunk:
//   - 1 LDG:  lanes 0-15 read ranks_depth, lanes 16-31 read ranks_feat
//   - 1 LDG:  lanes 0-15 gather the 16 depth scalars
//   - 16 LDG.128: per point, lanes 0-19 read the whole 320B feat row
// Intervals are disjoint BEV bins -> plain stores, no atomics.
// ---------------------------------------------------------------------------
__global__ void __launch_bounds__(256)
bev_pool_kernel(const float* __restrict__ depth,
                const float* __restrict__ feat,
                const int*   __restrict__ ranks_depth,
                const int*   __restrict__ ranks_feat,
                const int*   __restrict__ ranks_bev,
                const int*   __restrict__ istart,
                const int*   __restrict__ ilen,
                int n_intervals,
                float* __restrict__ out) {
    int gwarp = (blockIdx.x * blockDim.x + threadIdx.x) >> 5;
    int lane  = threadIdx.x & 31;
    if (gwarp >= n_intervals) return;

    const int start = istart[gwarp];
    const int len   = ilen[gwarp];

    const bool fa = (lane < 20);                 // feat-active lanes (20*4 = 80 ch)
    const float4* __restrict__ fbase = (const float4*)feat;

    float4 acc = make_float4(0.f, 0.f, 0.f, 0.f);

    const int lo16 = lane & 15;                  // 0..15 within each half-warp

    int i = 0;
    const int nfull = len & ~15;

    // ---- full 16-point chunks ----
    for (; i < nfull; i += 16) {
        const int p = start + i;
        // lanes 0-15: ranks_depth[p+lane]; lanes 16-31: ranks_feat[p+lane-16]
        const int* ip = (lane < 16) ? (ranks_depth + p + lane)
                                    : (ranks_feat  + p + lo16);
        int idxv = __ldg(ip);
        // lanes 0-15 gather depth scalars for the 16 points
        float dv = 0.f;
        if (lane < 16) dv = __ldg(&depth[idxv]);

        #pragma unroll
        for (int j = 0; j < 16; j++) {
            float d  = __shfl_sync(0xffffffffu, dv,   j);
            int   rf = __shfl_sync(0xffffffffu, idxv, 16 + j);
            if (fa) {
                float4 f = __ldg(fbase + (size_t)rf * 20 + lane);
                acc.x = fmaf(d, f.x, acc.x);
                acc.y = fmaf(d, f.y, acc.y);
                acc.z = fmaf(d, f.z, acc.z);
                acc.w = fmaf(d, f.w, acc.w);
            }
        }
    }

    // ---- tail chunk (< 16 points) ----
    if (i < len) {
        const int n = len - i;
        const int p = start + i;
        bool valid = lo16 < n;
        const int* ip = (lane < 16) ? (ranks_depth + p + lo16)
                                    : (ranks_feat  + p + lo16);
        int idxv = valid ? __ldg(ip) : 0;
        float dv = 0.f;
        if (lane < 16 && valid) dv = __ldg(&depth[idxv]);

        for (int j = 0; j < n; j++) {
            float d  = __shfl_sync(0xffffffffu, dv,   j);
            int   rf = __shfl_sync(0xffffffffu, idxv, 16 + j);
            if (fa) {
                float4 f = __ldg(fbase + (size_t)rf * 20 + lane);
                acc.x = fmaf(d, f.x, acc.x);
                acc.y = fmaf(d, f.y, acc.y);
                acc.z = fmaf(d, f.z, acc.z);
                acc.w = fmaf(d, f.w, acc.w);
            }
        }
    }

    // ---- store: output layout (B, C, Dz, Dy, Dx); bev = b*S + s ----
    if (fa) {
        int bev = __ldg(&ranks_bev[start]);
        int b   = bev / S_;
        int s   = bev - b * S_;
        float* o = out + (size_t)b * C_ * S_ + s;
        int c = lane * 4;
        o[(size_t)(c + 0) * S_] = acc.x;
        o[(size_t)(c + 1) * S_] = acc.y;
        o[(size_t)(c + 2) * S_] = acc.z;
        o[(size_t)(c + 3) * S_] = acc.w;
    }
}

// ---------------------------------------------------------------------------
extern "C" void kernel_launch(void* const* d_in, const int* in_sizes, int n_in,
                              void* d_out, int out_size) {
    const float* depth = nullptr;
    const float* feat  = nullptr;
    const int*   ranks[3] = {nullptr, nullptr, nullptr};
    int nrk = 0;
    const int* small_arr[2] = {nullptr, nullptr};
    int small_sz[2] = {0, 0};
    int nsmall = 0;

    for (int i = 0; i < n_in; i++) {
        int sz = in_sizes[i];
        if (sz == N_DEPTH && !depth) {
            depth = (const float*)d_in[i];
        } else if (sz == N_FEAT && !feat) {
            feat = (const float*)d_in[i];
        } else if (sz == N_PTS && nrk < 3) {
            ranks[nrk++] = (const int*)d_in[i];   // order: depths, feats, bevs
        } else if (sz == 5) {
            // bev_feat_shape metadata — compile-time constants here
        } else if (nsmall < 2) {
            small_arr[nsmall] = (const int*)d_in[i];  // order: starts, lengths
            small_sz[nsmall] = sz;
            nsmall++;
        }
    }

    const int* istart = small_arr[0];
    const int* ilen   = small_arr[1];
    int n_intervals   = small_sz[0];

    float* out = (float*)d_out;

    // 1) zero the output
    int n4 = out_size / 4;
    zero_kernel<<<256, 256>>>((float4*)out, n4);

    // 2) pooled gather-multiply-store, one warp per interval
    const int threads = 256;                    // 8 warps per block
    int blocks = (n_intervals + 7) / 8;
    if (blocks < 1) blocks = 1;
    bev_pool_kernel<<<blocks, threads>>>(depth, feat,
                                         ranks[0], ranks[1], ranks[2],
                                         istart, ilen, n_intervals, out);
}